// round 1
// baseline (speedup 1.0000x reference)
#include <cuda_runtime.h>
#include <cuda_bf16.h>
#include <cstdint>

// Focal loss (log10 variant) mean over 28.3M elements.
// Strictly HBM-bound: 226.5 MB read, one scalar out.
// Two-pass deterministic reduction: main kernel -> per-block partials in
// __device__ global, tiny second kernel -> mean.

#define NBLOCKS   1024
#define NTHREADS  256

__device__ float g_partials[NBLOCKS];

__device__ __forceinline__ float focal_elem(float p, int y) {
    // pos: y == 1 (targets are {0,1})
    bool  pos = (y != 0);
    float pt  = pos ? p : 1.0f - p;
    float om  = 1.0f - pt;
    // -log10(pt) = -log2(pt) * log10(2)
    float lt  = -__log2f(pt) * 0.3010299956639812f;
    float w   = pos ? 0.9f : 0.1f;
    return w * om * om * lt;
}

__global__ void __launch_bounds__(NTHREADS)
focal_main_kernel(const float4* __restrict__ p4,
                  const int4*   __restrict__ t4,
                  int nvec, int ntail,
                  const float* __restrict__ p_tail,
                  const int*   __restrict__ t_tail) {
    float acc = 0.0f;
    int stride = gridDim.x * blockDim.x;
    for (int i = blockIdx.x * blockDim.x + threadIdx.x; i < nvec; i += stride) {
        float4 p = p4[i];
        int4   t = t4[i];
        acc += focal_elem(p.x, t.x);
        acc += focal_elem(p.y, t.y);
        acc += focal_elem(p.z, t.z);
        acc += focal_elem(p.w, t.w);
    }
    // tail (N not divisible by 4) — handled by block 0 threads
    if (blockIdx.x == 0) {
        for (int i = threadIdx.x; i < ntail; i += blockDim.x)
            acc += focal_elem(p_tail[i], t_tail[i]);
    }

    // warp reduce
    #pragma unroll
    for (int off = 16; off > 0; off >>= 1)
        acc += __shfl_xor_sync(0xFFFFFFFFu, acc, off);

    __shared__ float smem[NTHREADS / 32];
    int lane = threadIdx.x & 31;
    int wid  = threadIdx.x >> 5;
    if (lane == 0) smem[wid] = acc;
    __syncthreads();

    if (wid == 0) {
        float v = (lane < NTHREADS / 32) ? smem[lane] : 0.0f;
        #pragma unroll
        for (int off = 4; off > 0; off >>= 1)
            v += __shfl_xor_sync(0xFFFFFFFFu, v, off);
        if (lane == 0) g_partials[blockIdx.x] = v;
    }
}

__global__ void __launch_bounds__(NBLOCKS)
focal_reduce_kernel(float* __restrict__ out, float inv_n) {
    float v = g_partials[threadIdx.x];
    #pragma unroll
    for (int off = 16; off > 0; off >>= 1)
        v += __shfl_xor_sync(0xFFFFFFFFu, v, off);

    __shared__ float smem[NBLOCKS / 32];
    int lane = threadIdx.x & 31;
    int wid  = threadIdx.x >> 5;
    if (lane == 0) smem[wid] = v;
    __syncthreads();

    if (wid == 0) {
        float s = (lane < NBLOCKS / 32) ? smem[lane] : 0.0f;
        #pragma unroll
        for (int off = 16; off > 0; off >>= 1)
            s += __shfl_xor_sync(0xFFFFFFFFu, s, off);
        if (lane == 0) out[0] = s * inv_n;
    }
}

extern "C" void kernel_launch(void* const* d_in, const int* in_sizes, int n_in,
                              void* d_out, int out_size) {
    const float* p = (const float*)d_in[0];
    const int*   t = (const int*)d_in[1];
    int n = in_sizes[0];

    int nvec  = n >> 2;          // float4 groups
    int ntail = n - (nvec << 2); // leftover elements

    focal_main_kernel<<<NBLOCKS, NTHREADS>>>(
        (const float4*)p, (const int4*)t, nvec, ntail,
        p + (nvec << 2), t + (nvec << 2));

    focal_reduce_kernel<<<1, NBLOCKS>>>((float*)d_out, 1.0f / (float)n);
}

// round 2
// speedup vs baseline: 1.0147x; 1.0147x over previous
#include <cuda_runtime.h>
#include <cuda_bf16.h>
#include <cstdint>

// Focal loss (log10 variant) mean over 28.3M elems. HBM-bound: 226.5 MB read.
// Single fused kernel: grid-stride vectorized pass -> per-block partials ->
// last-arriving block does the deterministic final reduction and writes d_out.

#define NBLOCKS   1024
#define NTHREADS  256

__device__ float        g_partials[NBLOCKS];
__device__ unsigned int g_count = 0;

__device__ __forceinline__ float focal_elem(float p, int y) {
    bool  pos = (y != 0);
    float pt  = pos ? p : 1.0f - p;
    float om  = 1.0f - pt;
    // -log10(pt) = -log2(pt) * log10(2)
    float lt  = -__log2f(pt) * 0.3010299956639812f;
    float w   = pos ? 0.9f : 0.1f;
    return w * om * om * lt;
}

__global__ void __launch_bounds__(NTHREADS)
focal_fused_kernel(const float4* __restrict__ p4,
                   const int4*   __restrict__ t4,
                   int nvec, int ntail,
                   const float* __restrict__ p_tail,
                   const int*   __restrict__ t_tail,
                   float* __restrict__ out, float inv_n) {
    float acc = 0.0f;
    int stride = gridDim.x * blockDim.x;
    for (int i = blockIdx.x * blockDim.x + threadIdx.x; i < nvec; i += stride) {
        float4 p = p4[i];
        int4   t = t4[i];
        acc += focal_elem(p.x, t.x);
        acc += focal_elem(p.y, t.y);
        acc += focal_elem(p.z, t.z);
        acc += focal_elem(p.w, t.w);
    }
    if (blockIdx.x == 0) {
        for (int i = threadIdx.x; i < ntail; i += blockDim.x)
            acc += focal_elem(p_tail[i], t_tail[i]);
    }

    // intra-block reduce
    #pragma unroll
    for (int off = 16; off > 0; off >>= 1)
        acc += __shfl_xor_sync(0xFFFFFFFFu, acc, off);

    __shared__ float smem[NTHREADS / 32];
    int lane = threadIdx.x & 31;
    int wid  = threadIdx.x >> 5;
    if (lane == 0) smem[wid] = acc;
    __syncthreads();

    __shared__ bool s_last;
    if (threadIdx.x == 0) {
        float v = 0.0f;
        #pragma unroll
        for (int w = 0; w < NTHREADS / 32; w++) v += smem[w];
        g_partials[blockIdx.x] = v;
        __threadfence();
        unsigned int prev = atomicAdd(&g_count, 1u);
        s_last = (prev == (unsigned int)(gridDim.x - 1));
    }
    __syncthreads();

    if (s_last) {
        // deterministic final reduction: fixed per-thread order, then tree
        float v = 0.0f;
        #pragma unroll
        for (int k = threadIdx.x; k < NBLOCKS; k += NTHREADS)
            v += g_partials[k];

        #pragma unroll
        for (int off = 16; off > 0; off >>= 1)
            v += __shfl_xor_sync(0xFFFFFFFFu, v, off);

        if (lane == 0) smem[wid] = v;
        __syncthreads();

        if (wid == 0) {
            float s = (lane < NTHREADS / 32) ? smem[lane] : 0.0f;
            #pragma unroll
            for (int off = 4; off > 0; off >>= 1)
                s += __shfl_xor_sync(0xFFFFFFFFu, s, off);
            if (lane == 0) {
                out[0] = s * inv_n;
                g_count = 0;           // reset for next graph replay
                __threadfence();
            }
        }
    }
}

extern "C" void kernel_launch(void* const* d_in, const int* in_sizes, int n_in,
                              void* d_out, int out_size) {
    const float* p = (const float*)d_in[0];
    const int*   t = (const int*)d_in[1];
    int n = in_sizes[0];

    int nvec  = n >> 2;
    int ntail = n - (nvec << 2);

    focal_fused_kernel<<<NBLOCKS, NTHREADS>>>(
        (const float4*)p, (const int4*)t, nvec, ntail,
        p + (nvec << 2), t + (nvec << 2),
        (float*)d_out, 1.0f / (float)n);
}